// round 1
// baseline (speedup 1.0000x reference)
#include <cuda_runtime.h>
#include <cuda_bf16.h>

#define L   2048
#define D   64
#define BQ  64      // queries per block == threads per block
#define TK  64      // key tile
#define CH  16      // softmax chunk (rescale amortization)

using u64 = unsigned long long;

__device__ __forceinline__ u64 pack2(float lo, float hi) {
    u64 r; asm("mov.b64 %0, {%1, %2};" : "=l"(r) : "f"(lo), "f"(hi)); return r;
}
__device__ __forceinline__ void unpack2(u64 v, float &lo, float &hi) {
    asm("mov.b64 {%0, %1}, %2;" : "=f"(lo), "=f"(hi) : "l"(v));
}
// d = a * b + d   (packed fp32x2, sm_100+)
__device__ __forceinline__ void fma2(u64 &d, u64 a, u64 b) {
    asm("fma.rn.f32x2 %0, %1, %2, %0;" : "+l"(d) : "l"(a), "l"(b));
}
// d = d * a
__device__ __forceinline__ void mul2(u64 &d, u64 a) {
    asm("mul.rn.f32x2 %0, %0, %1;" : "+l"(d) : "l"(a));
}

__global__ void __launch_bounds__(BQ)
attn_f32x2_kernel(const float* __restrict__ Q,
                  const float* __restrict__ K,
                  const float* __restrict__ V,
                  float* __restrict__ O)
{
    __shared__ float Ks[TK * D];
    __shared__ float Vs[TK * D];

    const int b  = blockIdx.y;
    const int qi = blockIdx.x * BQ + threadIdx.x;
    const float scale = 0.125f;   // 1/sqrt(64)

    // Load this thread's query row, pre-scaled, packed into f32x2 pairs.
    const float* qp = Q + ((size_t)b * L + qi) * D;
    u64 qv[D / 2];
#pragma unroll
    for (int i = 0; i < D / 4; i++) {
        float4 t = reinterpret_cast<const float4*>(qp)[i];
        qv[2 * i]     = pack2(t.x * scale, t.y * scale);
        qv[2 * i + 1] = pack2(t.z * scale, t.w * scale);
    }

    u64 acc[D / 2];
#pragma unroll
    for (int i = 0; i < D / 2; i++) acc[i] = 0ull;   // (0.f, 0.f)

    float m = -1e30f;
    float l = 0.f;

    const float4* Kg  = reinterpret_cast<const float4*>(K + (size_t)b * L * D);
    const float4* Vg  = reinterpret_cast<const float4*>(V + (size_t)b * L * D);
    float4* Ks4 = reinterpret_cast<float4*>(Ks);
    float4* Vs4 = reinterpret_cast<float4*>(Vs);

#pragma unroll 1
    for (int kt = 0; kt < L; kt += TK) {
        __syncthreads();   // previous tile's reads complete before overwrite
        const int base = kt * (D / 4);
#pragma unroll
        for (int i = 0; i < (TK * D / 4) / BQ; i++) {   // 16 float4 per thread
            Ks4[threadIdx.x + i * BQ] = Kg[base + threadIdx.x + i * BQ];
            Vs4[threadIdx.x + i * BQ] = Vg[base + threadIdx.x + i * BQ];
        }
        __syncthreads();

#pragma unroll 1
        for (int j0 = 0; j0 < TK; j0 += CH) {
            float s[CH];
            // ---- scores for CH keys (broadcast LDS of K rows) ----
#pragma unroll
            for (int jj = 0; jj < CH; jj++) {
                const u64* kr = reinterpret_cast<const u64*>(Ks + (j0 + jj) * D);
                u64 a0 = 0ull, a1 = 0ull, a2 = 0ull, a3 = 0ull;
#pragma unroll
                for (int i = 0; i < D / 2; i += 4) {
                    fma2(a0, qv[i],     kr[i]);
                    fma2(a1, qv[i + 1], kr[i + 1]);
                    fma2(a2, qv[i + 2], kr[i + 2]);
                    fma2(a3, qv[i + 3], kr[i + 3]);
                }
                float x0, x1, x2, x3, x4, x5, x6, x7;
                unpack2(a0, x0, x1); unpack2(a1, x2, x3);
                unpack2(a2, x4, x5); unpack2(a3, x6, x7);
                s[jj] = ((x0 + x1) + (x2 + x3)) + ((x4 + x5) + (x6 + x7));
            }
            // ---- online softmax update (one rescale per CH keys) ----
            float cmax = s[0];
#pragma unroll
            for (int jj = 1; jj < CH; jj++) cmax = fmaxf(cmax, s[jj]);
            float mnew = fmaxf(m, cmax);
            float corr = __expf(m - mnew);   // first chunk: exp(-1e30) = 0
            m = mnew;
            l *= corr;
            u64 corr2 = pack2(corr, corr);
#pragma unroll
            for (int i = 0; i < D / 2; i++) mul2(acc[i], corr2);
            // ---- P·V accumulation ----
#pragma unroll
            for (int jj = 0; jj < CH; jj++) {
                float p = __expf(s[jj] - m);
                l += p;
                u64 p2 = pack2(p, p);
                const u64* vr = reinterpret_cast<const u64*>(Vs + (j0 + jj) * D);
#pragma unroll
                for (int i = 0; i < D / 2; i++) fma2(acc[i], p2, vr[i]);
            }
        }
    }

    const float inv = 1.f / l;
    float* op = O + ((size_t)b * L + qi) * D;
#pragma unroll
    for (int i = 0; i < D / 2; i++) {
        float lo, hi; unpack2(acc[i], lo, hi);
        reinterpret_cast<float2*>(op)[i] = make_float2(lo * inv, hi * inv);
    }
}

extern "C" void kernel_launch(void* const* d_in, const int* in_sizes, int n_in,
                              void* d_out, int out_size)
{
    const float* Q = (const float*)d_in[0];
    const float* K = (const float*)d_in[1];
    const float* V = (const float*)d_in[2];
    float* O = (float*)d_out;

    const int B = in_sizes[0] / (L * D);   // 8
    dim3 grid(L / BQ, B);
    attn_f32x2_kernel<<<grid, BQ>>>(Q, K, V, O);
}